// round 8
// baseline (speedup 1.0000x reference)
#include <cuda_runtime.h>
#include <math.h>
#include <stdint.h>

// Problem constants
#define BB    8
#define CC    512
#define NN    1024        // H*W = 32*32
#define HEADS 8
#define DK    64
#define QKVC  1536        // HEADS * DK * 3
#define SCL2E 0.18033688f // DK^-0.5 * log2(e)

// Scratch (device globals; no allocation allowed)
__device__ float g_qkv[BB * NN * QKVC];   // [b*N+n][1536], per head: q(64) k(64) v(64)
__device__ float g_att[BB * NN * CC];     // [b*N+n][h*64+d]

// ---------------------------------------------------------------------------
// Helpers
// ---------------------------------------------------------------------------
__device__ __forceinline__ float ex2(float x) {
    float y;
    asm("ex2.approx.f32 %0, %1;" : "=f"(y) : "f"(x));
    return y;
}
// bf16 split: f = hi + lo; hi = truncate-to-bf16 (exact), lo = rn(residual)
__device__ __forceinline__ uint32_t hi2(float f0, float f1) {  // {bf16(f0)|bf16(f1)<<16}
    uint32_t r;
    asm("prmt.b32 %0, %1, %2, 0x7632;" : "=r"(r)
        : "r"(__float_as_uint(f0)), "r"(__float_as_uint(f1)));
    return r;
}
__device__ __forceinline__ float hif(float f) {
    return __uint_as_float(__float_as_uint(f) & 0xFFFF0000u);
}
__device__ __forceinline__ uint32_t lo2(float f0, float f1) {
    uint32_t r;
    asm("cvt.rn.bf16x2.f32 %0, %1, %2;" : "=r"(r)
        : "f"(f1 - hif(f1)), "f"(f0 - hif(f0)));
    return r;
}
__device__ __forceinline__ uint16_t hi1(float f) { return (uint16_t)(__float_as_uint(f) >> 16); }
__device__ __forceinline__ uint16_t lo1(float f) {
    uint32_t r;
    float res = f - hif(f);
    asm("cvt.rn.bf16x2.f32 %0, %1, %2;" : "=r"(r) : "f"(res), "f"(res));
    return (uint16_t)r;
}

__device__ __forceinline__ void ldmx4t(uint32_t addr, uint32_t& r0, uint32_t& r1,
                                       uint32_t& r2, uint32_t& r3) {
    asm volatile("ldmatrix.sync.aligned.m8n8.x4.trans.shared.b16 {%0,%1,%2,%3}, [%4];"
                 : "=r"(r0), "=r"(r1), "=r"(r2), "=r"(r3) : "r"(addr));
}
__device__ __forceinline__ void ldmx4(uint32_t addr, uint32_t* r) {
    asm volatile("ldmatrix.sync.aligned.m8n8.x4.shared.b16 {%0,%1,%2,%3}, [%4];"
                 : "=r"(r[0]), "=r"(r[1]), "=r"(r[2]), "=r"(r[3]) : "r"(addr));
}
__device__ __forceinline__ void mma16816(float* d, const uint32_t* a, const uint32_t* b) {
    asm volatile("mma.sync.aligned.m16n8k16.row.col.f32.bf16.bf16.f32 "
                 "{%0,%1,%2,%3}, {%4,%5,%6,%7}, {%8,%9}, {%0,%1,%2,%3};"
                 : "+f"(d[0]), "+f"(d[1]), "+f"(d[2]), "+f"(d[3])
                 : "r"(a[0]), "r"(a[1]), "r"(a[2]), "r"(a[3]), "r"(b[0]), "r"(b[1]));
}
__device__ __forceinline__ void mma_b(float* d, const uint32_t* a, uint32_t b0, uint32_t b1) {
    asm volatile("mma.sync.aligned.m16n8k16.row.col.f32.bf16.bf16.f32 "
                 "{%0,%1,%2,%3}, {%4,%5,%6,%7}, {%8,%9}, {%0,%1,%2,%3};"
                 : "+f"(d[0]), "+f"(d[1]), "+f"(d[2]), "+f"(d[3])
                 : "r"(a[0]), "r"(a[1]), "r"(a[2]), "r"(a[3]), "r"(b0), "r"(b1));
}

// ---------------------------------------------------------------------------
// Kernel 1: QKV GEMM via tensor cores (bf16x3 split).
// ---------------------------------------------------------------------------
#define KTILE  (32 * 136)
#define KBYTES (KTILE * 2)
#define BUFBYTES (4 * KBYTES)

__global__ __launch_bounds__(256, 2) void k_qkv(const float* __restrict__ x,
                                                const float* __restrict__ Wq,
                                                const float* __restrict__ bq)
{
    extern __shared__ __align__(16) uint16_t smq[];

    const int tid  = threadIdx.x;
    const int lane = tid & 31;
    const int wid  = tid >> 5;
    const int bx   = blockIdx.x;
    const int by   = blockIdx.y;
    const int b    = by >> 3;
    const int n0   = (by & 7) << 7;
    const int c0   = bx * 128;

    const uint32_t sbase = (uint32_t)__cvta_generic_to_shared(smq);

    const int lk  = tid >> 3;
    const int lmf = (tid & 7) * 4;

    const float* pA = x  + (size_t)b * CC * NN + (size_t)lk * NN + n0 + lmf;
    const float* pW = Wq + (size_t)lk * QKVC + c0 + lmf;

    const int wm = wid >> 2;
    const int wn = wid & 3;
    const uint32_t aOff = ((lane & 7) + ((lane >> 4) << 3)) * 272
                        + (uint32_t)(wm * 128) + ((lane >> 3) & 1) * 16;
    const uint32_t bOff = ((lane & 7) + (((lane >> 3) & 1) << 3)) * 272
                        + (uint32_t)(wn * 64) + (lane >> 4) * 16;

    float acc[4][4][4];
#pragma unroll
    for (int i = 0; i < 4; i++)
#pragma unroll
        for (int j = 0; j < 4; j++)
#pragma unroll
            for (int e = 0; e < 4; e++) acc[i][j][e] = 0.f;

    {
        uint16_t* s = smq;
        float4 a4[4], w4[4];
#pragma unroll
        for (int j = 0; j < 4; j++) {
            a4[j] = *(const float4*)&pA[32 * j];
            w4[j] = *(const float4*)&pW[32 * j];
        }
#pragma unroll
        for (int j = 0; j < 4; j++) {
            int idx = lk * 136 + lmf + 32 * j;
            *(uint2*)&s[idx]             = make_uint2(hi2(a4[j].x, a4[j].y), hi2(a4[j].z, a4[j].w));
            *(uint2*)&s[KTILE + idx]     = make_uint2(lo2(a4[j].x, a4[j].y), lo2(a4[j].z, a4[j].w));
            *(uint2*)&s[2 * KTILE + idx] = make_uint2(hi2(w4[j].x, w4[j].y), hi2(w4[j].z, w4[j].w));
            *(uint2*)&s[3 * KTILE + idx] = make_uint2(lo2(w4[j].x, w4[j].y), lo2(w4[j].z, w4[j].w));
        }
    }
    __syncthreads();

    for (int s = 0; s < 16; s++) {
        const int cur = s & 1;
        float4 a4[4], w4[4];
        if (s < 15) {
            const size_t ko = (size_t)(s + 1) * 32;
#pragma unroll
            for (int j = 0; j < 4; j++) {
                a4[j] = *(const float4*)&pA[ko * NN + 32 * j];
                w4[j] = *(const float4*)&pW[ko * QKVC + 32 * j];
            }
        }

        const uint32_t base = sbase + (uint32_t)cur * BUFBYTES;
#pragma unroll
        for (int ks = 0; ks < 2; ks++) {
            uint32_t ahi[4][4], alo[4][4], bhi[4][2], blo[4][2];
#pragma unroll
            for (int i = 0; i < 4; i++) {
                uint32_t addr = base + aOff + ks * 4352 + i * 32;
                ldmx4t(addr, ahi[i][0], ahi[i][1], ahi[i][2], ahi[i][3]);
                ldmx4t(addr + KBYTES, alo[i][0], alo[i][1], alo[i][2], alo[i][3]);
            }
#pragma unroll
            for (int j2 = 0; j2 < 2; j2++) {
                uint32_t addr = base + 2 * KBYTES + bOff + ks * 4352 + j2 * 32;
                ldmx4t(addr, bhi[2 * j2][0], bhi[2 * j2][1], bhi[2 * j2 + 1][0], bhi[2 * j2 + 1][1]);
                ldmx4t(addr + KBYTES, blo[2 * j2][0], blo[2 * j2][1], blo[2 * j2 + 1][0], blo[2 * j2 + 1][1]);
            }
#pragma unroll
            for (int i = 0; i < 4; i++)
#pragma unroll
                for (int jn = 0; jn < 4; jn++) {
                    mma16816(acc[i][jn], ahi[i], bhi[jn]);
                    mma16816(acc[i][jn], ahi[i], blo[jn]);
                    mma16816(acc[i][jn], alo[i], bhi[jn]);
                }
        }

        if (s < 15) {
            uint16_t* d = smq + (1 - cur) * (BUFBYTES / 2);
#pragma unroll
            for (int j = 0; j < 4; j++) {
                int idx = lk * 136 + lmf + 32 * j;
                *(uint2*)&d[idx]             = make_uint2(hi2(a4[j].x, a4[j].y), hi2(a4[j].z, a4[j].w));
                *(uint2*)&d[KTILE + idx]     = make_uint2(lo2(a4[j].x, a4[j].y), lo2(a4[j].z, a4[j].w));
                *(uint2*)&d[2 * KTILE + idx] = make_uint2(hi2(w4[j].x, w4[j].y), hi2(w4[j].z, w4[j].w));
                *(uint2*)&d[3 * KTILE + idx] = make_uint2(lo2(w4[j].x, w4[j].y), lo2(w4[j].z, w4[j].w));
            }
            __syncthreads();
        }
    }

    const int g   = lane >> 2;
    const int tig = lane & 3;
#pragma unroll
    for (int i = 0; i < 4; i++) {
        int m = by * 128 + wm * 64 + i * 16 + g;
#pragma unroll
        for (int jn = 0; jn < 4; jn++) {
            int c = c0 + wn * 32 + jn * 8 + tig * 2;
            float2 bias = *(const float2*)&bq[c];
            float2 v0 = make_float2(acc[i][jn][0] + bias.x, acc[i][jn][1] + bias.y);
            float2 v1 = make_float2(acc[i][jn][2] + bias.x, acc[i][jn][3] + bias.y);
            *(float2*)&g_qkv[(size_t)m * QKVC + c]       = v0;
            *(float2*)&g_qkv[(size_t)(m + 8) * QKVC + c] = v1;
        }
    }
}

// ---------------------------------------------------------------------------
// Kernel 2: attention via tensor cores (bf16x3 split), no online softmax.
// Fused S->exp->P->PV per 16-key group: sacc live range is 8 floats, allowing
// the 128-reg cap and 2 CTAs/SM.
// ---------------------------------------------------------------------------
#define AQ_STR 72
#define AV_STR 136
#define A_QLO  9216
#define A_KHI  18432
#define A_KLO  27648
#define A_VHI  36864
#define A_VLO  45568
#define A_SMEM_BYTES 108544

__global__ __launch_bounds__(256, 2) void k_attn()
{
    extern __shared__ __align__(16) uint16_t sma[];
    const int tid  = threadIdx.x;
    const int lane = tid & 31;
    const int wid  = tid >> 5;
    const int qt   = blockIdx.x;   // 0..7
    const int h    = blockIdx.y;
    const int b    = blockIdx.z;
    const size_t head = (size_t)b * NN * QKVC + (size_t)h * (3 * DK);
    const uint32_t sb = (uint32_t)__cvta_generic_to_shared(sma);

    // ---- load Q tile (scaled), split to bf16 hi/lo ----
    {
        const int row = tid >> 1;
        const int d0  = (tid & 1) * 32;
        const float* src = &g_qkv[head + (size_t)(qt * 128 + row) * QKVC + d0];
        uint16_t* qh = sma + row * AQ_STR + d0;
#pragma unroll
        for (int i = 0; i < 8; i++) {
            float4 v = *(const float4*)&src[4 * i];
            v.x *= SCL2E; v.y *= SCL2E; v.z *= SCL2E; v.w *= SCL2E;
            *(uint2*)&qh[4 * i]         = make_uint2(hi2(v.x, v.y), hi2(v.z, v.w));
            *(uint2*)&qh[A_QLO + 4 * i] = make_uint2(lo2(v.x, v.y), lo2(v.z, v.w));
        }
    }
    __syncthreads();

    // ---- Q fragments, loaded once: [plane][kstep][4] ----
    uint32_t qf[2][4][4];
    {
        const uint32_t qa = sb + (wid * 16 + (lane & 15)) * 144 + (lane >> 4) * 16;
#pragma unroll
        for (int j = 0; j < 4; j++) {
            ldmx4(qa + j * 32, qf[0][j]);
            ldmx4(qa + j * 32 + A_QLO * 2, qf[1][j]);
        }
    }

    float oacc[8][4];
#pragma unroll
    for (int i = 0; i < 8; i++)
#pragma unroll
        for (int e = 0; e < 4; e++) oacc[i][e] = 0.f;
    float li0 = 0.f, li1 = 0.f;

    const uint32_t kB = sb + A_KHI * 2 + ((lane & 7) + ((lane >> 4) << 3)) * 144
                      + ((lane >> 3) & 1) * 16;
    const uint32_t vB = sb + A_VHI * 2 + ((lane & 7) + ((lane >> 4) << 3)) * 272
                      + ((lane >> 3) & 1) * 16;

    for (int kt = 0; kt < 8; kt++) {
        __syncthreads();   // previous iteration's smem reads done
        {
            const int key = tid >> 1;
            const int d0  = (tid & 1) * 32;
            const float* kp = &g_qkv[head + (size_t)(kt * 128 + key) * QKVC + 64 + d0];
            uint16_t* khp = sma + A_KHI + key * AQ_STR + d0;
#pragma unroll
            for (int i = 0; i < 8; i++) {
                float4 v = *(const float4*)&kp[4 * i];
                *(uint2*)&khp[4 * i]                   = make_uint2(hi2(v.x, v.y), hi2(v.z, v.w));
                *(uint2*)&khp[(A_KLO - A_KHI) + 4 * i] = make_uint2(lo2(v.x, v.y), lo2(v.z, v.w));
            }
            const float* vp = kp + 64;
#pragma unroll
            for (int i = 0; i < 8; i++) {
                float4 v = *(const float4*)&vp[4 * i];
                int d = d0 + 4 * i;
                sma[A_VHI + (d + 0) * AV_STR + key] = hi1(v.x);
                sma[A_VHI + (d + 1) * AV_STR + key] = hi1(v.y);
                sma[A_VHI + (d + 2) * AV_STR + key] = hi1(v.z);
                sma[A_VHI + (d + 3) * AV_STR + key] = hi1(v.w);
                sma[A_VLO + (d + 0) * AV_STR + key] = lo1(v.x);
                sma[A_VLO + (d + 1) * AV_STR + key] = lo1(v.y);
                sma[A_VLO + (d + 2) * AV_STR + key] = lo1(v.z);
                sma[A_VLO + (d + 3) * AV_STR + key] = lo1(v.w);
            }
        }
        __syncthreads();

        // ---- fused per 16-key group: S (2 n8-tiles) -> exp -> P -> PV ----
#pragma unroll
        for (int nt2 = 0; nt2 < 8; nt2++) {
            float s0[4], s1[4];
#pragma unroll
            for (int e = 0; e < 4; e++) { s0[e] = 0.f; s1[e] = 0.f; }

#pragma unroll
            for (int j = 0; j < 4; j++) {
                uint32_t kh[4], kl[4];
                uint32_t a = kB + nt2 * (16 * 144) + j * 32;
                ldmx4(a, kh);
                ldmx4(a + (A_KLO - A_KHI) * 2, kl);
                mma_b(s0, qf[0][j], kh[0], kh[1]);
                mma_b(s0, qf[0][j], kl[0], kl[1]);
                mma_b(s0, qf[1][j], kh[0], kh[1]);
                mma_b(s1, qf[0][j], kh[2], kh[3]);
                mma_b(s1, qf[0][j], kl[2], kl[3]);
                mma_b(s1, qf[1][j], kh[2], kh[3]);
            }

#pragma unroll
            for (int e = 0; e < 4; e++) { s0[e] = ex2(s0[e]); s1[e] = ex2(s1[e]); }
            li0 += (s0[0] + s0[1]) + (s1[0] + s1[1]);
            li1 += (s0[2] + s0[3]) + (s1[2] + s1[3]);

            uint32_t ph[4], pl[4];
            ph[0] = hi2(s0[0], s0[1]); ph[1] = hi2(s0[2], s0[3]);
            ph[2] = hi2(s1[0], s1[1]); ph[3] = hi2(s1[2], s1[3]);
            pl[0] = lo2(s0[0], s0[1]); pl[1] = lo2(s0[2], s0[3]);
            pl[2] = lo2(s1[0], s1[1]); pl[3] = lo2(s1[2], s1[3]);

#pragma unroll
            for (int dt2 = 0; dt2 < 4; dt2++) {
                uint32_t vh[4], vl[4];
                uint32_t a = vB + dt2 * (16 * 272) + nt2 * 32;
                ldmx4(a, vh);
                ldmx4(a + (A_VLO - A_VHI) * 2, vl);
                mma_b(oacc[2 * dt2],     ph, vh[0], vh[1]);
                mma_b(oacc[2 * dt2],     ph, vl[0], vl[1]);
                mma_b(oacc[2 * dt2],     pl, vh[0], vh[1]);
                mma_b(oacc[2 * dt2 + 1], ph, vh[2], vh[3]);
                mma_b(oacc[2 * dt2 + 1], ph, vl[2], vl[3]);
                mma_b(oacc[2 * dt2 + 1], pl, vh[2], vh[3]);
            }
        }
    }

    // ---- reduce row sums over the 4 quad lanes, normalize, write ----
    li0 += __shfl_xor_sync(0xffffffffu, li0, 1);
    li0 += __shfl_xor_sync(0xffffffffu, li0, 2);
    li1 += __shfl_xor_sync(0xffffffffu, li1, 1);
    li1 += __shfl_xor_sync(0xffffffffu, li1, 2);
    const float inv0 = 1.f / li0;
    const float inv1 = 1.f / li1;

    const int g   = lane >> 2;
    const int tig = lane & 3;
    const int row = qt * 128 + wid * 16 + g;
    float* dst0 = &g_att[((size_t)(b * NN + row)) * CC + h * 64 + tig * 2];
    float* dst1 = dst0 + (size_t)8 * CC;
#pragma unroll
    for (int dt = 0; dt < 8; dt++) {
        *(float2*)&dst0[dt * 8] = make_float2(oacc[dt][0] * inv0, oacc[dt][1] * inv0);
        *(float2*)&dst1[dt * 8] = make_float2(oacc[dt][2] * inv1, oacc[dt][3] * inv1);
    }
}

// ---------------------------------------------------------------------------
// Kernel 3: out = att @ W_out + b_out + residual via tensor cores (bf16x3).
// ---------------------------------------------------------------------------
#define PJ_ALO    10240    // byte offsets within a stage
#define PJ_BHI    20480
#define PJ_BLO    29184
#define PJ_STAGEB 37888
#define PJ_SMEM   (2 * PJ_STAGEB)   // 75776 B

__global__ __launch_bounds__(256, 2) void k_proj(const float* __restrict__ Wo,
                                                 const float* __restrict__ bo,
                                                 const float* __restrict__ x,
                                                 float* __restrict__ out)
{
    extern __shared__ __align__(16) uint16_t smp[];
    const int tid  = threadIdx.x;
    const int lane = tid & 31;
    const int wid  = tid >> 5;
    const int bx   = blockIdx.x;    // bn tile 0..63
    const int by   = blockIdx.y;    // c tile 0..3
    const int b    = bx >> 3;
    const int c0   = by * 128;
    const int bn0  = bx * 128;
    const uint32_t sb = (uint32_t)__cvta_generic_to_shared(smp);

    const int am = tid >> 1;
    const int ak = (tid & 1) * 16;
    const float* pA = g_att + (size_t)(bn0 + am) * CC + ak;
    const int bk = tid >> 3;
    const int bn = (tid & 7) * 4;
    const float* pB = Wo + (size_t)bk * CC + c0 + bn;

    const int wm = wid >> 2;
    const int wn = wid & 3;
    const uint32_t aOff = (wm * 64 + (lane & 15)) * 80 + (lane >> 4) * 16;
    const uint32_t bOff = PJ_BHI + ((lane & 7) + (((lane >> 3) & 1) << 3)) * 272
                        + (uint32_t)(wn * 64) + (lane >> 4) * 16;

    float acc[4][4][4];
#pragma unroll
    for (int i = 0; i < 4; i++)
#pragma unroll
        for (int j = 0; j < 4; j++)
#pragma unroll
            for (int e = 0; e < 4; e++) acc[i][j][e] = 0.f;

    {
        uint16_t* s = smp;
#pragma unroll
        for (int i = 0; i < 4; i++) {
            float4 v = *(const float4*)&pA[4 * i];
            int ai = am * 40 + ak + 4 * i;
            *(uint2*)&s[ai]              = make_uint2(hi2(v.x, v.y), hi2(v.z, v.w));
            *(uint2*)&s[PJ_ALO / 2 + ai] = make_uint2(lo2(v.x, v.y), lo2(v.z, v.w));
            float4 w = *(const float4*)&pB[32 * i];
            int bi = bk * 136 + bn + 32 * i;
            *(uint2*)&s[PJ_BHI / 2 + bi] = make_uint2(hi2(w.x, w.y), hi2(w.z, w.w));
            *(uint2*)&s[PJ_BLO / 2 + bi] = make_uint2(lo2(w.x, w.y), lo2(w.z, w.w));
        }
    }
    __syncthreads();

    for (int s = 0; s < 16; s++) {
        const int cur = s & 1;
        float4 a4[4], w4[4];
        if (s < 15) {
#pragma unroll
            for (int i = 0; i < 4; i++) {
                a4[i] = *(const float4*)&pA[(s + 1) * 32 + 4 * i];
                w4[i] = *(const float4*)&pB[(size_t)(s + 1) * 32 * CC + 32 * i];
            }
        }

        const uint32_t base = sb + (uint32_t)cur * PJ_STAGEB;
#pragma unroll
        for (int ks = 0; ks < 2; ks++) {
            uint32_t ahi[4][4], alo[4][4], bhi[4][2], blo[4][2];
#pragma unroll
            for (int i = 0; i < 4; i++) {
                uint32_t a = base + aOff + i * (16 * 80) + ks * 32;
                ldmx4(a, ahi[i]);
                ldmx4(a + PJ_ALO, alo[i]);
            }
#pragma unroll
            for (int j2 = 0; j2 < 2; j2++) {
                uint32_t a = base + bOff + ks * 4352 + j2 * 32;
                ldmx4t(a, bhi[2 * j2][0], bhi[2 * j2][1], bhi[2 * j2 + 1][0], bhi[2 * j2 + 1][1]);
                ldmx4t(a + 8704, blo[2 * j2][0], blo[2 * j2][1], blo[2 * j2 + 1][0], blo[2 * j2 + 1][1]);
            }
#pragma unroll
            for (int i = 0; i < 4; i++)
#pragma unroll
                for (int jn = 0; jn < 4; jn++) {
                    mma16816(acc[i][jn], ahi[i], bhi[jn]);
                    mma16816(acc[i][jn], ahi[i], blo[jn]);
                    mma16816(acc[i][jn], alo[i], bhi[jn]);
                }
        }

        if (s < 15) {
            uint16_t* d = smp + (1 - cur) * (PJ_STAGEB / 2);
#pragma unroll
            for (int i = 0; i < 4; i++) {
                int ai = am * 40 + ak + 4 * i;
                *(uint2*)&d[ai]              = make_uint2(hi2(a4[i].x, a4[i].y), hi2(a4[i].z, a4[i].w));
                *(uint2*)&d[PJ_ALO / 2 + ai] = make_uint2(lo2(a4[i].x, a4[i].y), lo2(a4[i].z, a4[i].w));
                int bi = bk * 136 + bn + 32 * i;
                *(uint2*)&d[PJ_BHI / 2 + bi] = make_uint2(hi2(w4[i].x, w4[i].y), hi2(w4[i].z, w4[i].w));
                *(uint2*)&d[PJ_BLO / 2 + bi] = make_uint2(lo2(w4[i].x, w4[i].y), lo2(w4[i].z, w4[i].w));
            }
            __syncthreads();
        }
    }

    // ---- epilogue: transpose via smem, fused bias + residual, coalesced ----
    __syncthreads();
    float* S = (float*)smp;   // [128 c][stride 132] of m
    const int g   = lane >> 2;
    const int tig = lane & 3;
#pragma unroll
    for (int i = 0; i < 4; i++) {
        int m_l = wm * 64 + i * 16 + g;
#pragma unroll
        for (int jn = 0; jn < 4; jn++) {
            int c_l = wn * 32 + jn * 8 + tig * 2;
            S[c_l * 132 + m_l]           = acc[i][jn][0];
            S[(c_l + 1) * 132 + m_l]     = acc[i][jn][1];
            S[c_l * 132 + m_l + 8]       = acc[i][jn][2];
            S[(c_l + 1) * 132 + m_l + 8] = acc[i][jn][3];
        }
    }
    __syncthreads();
    {
        const int c_l  = tid >> 1;
        const int mseg = (tid & 1) * 64;
        const int c    = c0 + c_l;
        const float bias = bo[c];
        const int n0 = (bx & 7) * 128;
        const size_t basep = (size_t)b * CC * NN + (size_t)c * NN + n0 + mseg;
#pragma unroll
        for (int i = 0; i < 16; i++) {
            float4 v  = *(float4*)&S[c_l * 132 + mseg + 4 * i];
            float4 xr = *(const float4*)&x[basep + 4 * i];
            v.x += bias + xr.x; v.y += bias + xr.y;
            v.z += bias + xr.z; v.w += bias + xr.w;
            *(float4*)&out[basep + 4 * i] = v;
        }
    }
}

// ---------------------------------------------------------------------------
extern "C" void kernel_launch(void* const* d_in, const int* in_sizes, int n_in,
                              void* d_out, int out_size)
{
    const float* x  = (const float*)d_in[0];
    const float* Wq = (const float*)d_in[1];
    const float* bq = (const float*)d_in[2];
    const float* Wo = (const float*)d_in[3];
    const float* bo = (const float*)d_in[4];
    float* out = (float*)d_out;

    const int smem_qkv = 2 * BUFBYTES;   // 69632 B
    cudaFuncSetAttribute(k_qkv, cudaFuncAttributeMaxDynamicSharedMemorySize, smem_qkv);
    k_qkv<<<dim3(12, 64), 256, smem_qkv>>>(x, Wq, bq);

    cudaFuncSetAttribute(k_attn, cudaFuncAttributeMaxDynamicSharedMemorySize, A_SMEM_BYTES);
    k_attn<<<dim3(8, HEADS, BB), 256, A_SMEM_BYTES>>>();

    cudaFuncSetAttribute(k_proj, cudaFuncAttributeMaxDynamicSharedMemorySize, PJ_SMEM);
    k_proj<<<dim3(64, 4), 256, PJ_SMEM>>>(Wo, bo, x, out);
}

// round 9
// speedup vs baseline: 1.1224x; 1.1224x over previous
#include <cuda_runtime.h>
#include <math.h>
#include <stdint.h>

// Problem constants
#define BB    8
#define CC    512
#define NN    1024        // H*W = 32*32
#define HEADS 8
#define DK    64
#define QKVC  1536        // HEADS * DK * 3
#define SCL2E 0.18033688f // DK^-0.5 * log2(e)

// Scratch (device globals; no allocation allowed)
__device__ float g_qkv[BB * NN * QKVC];   // [b*N+n][1536], per head: q(64) k(64) v(64)
__device__ float g_att[BB * NN * CC];     // [b*N+n][h*64+d]

// ---------------------------------------------------------------------------
// Helpers
// ---------------------------------------------------------------------------
__device__ __forceinline__ float ex2(float x) {
    float y;
    asm("ex2.approx.f32 %0, %1;" : "=f"(y) : "f"(x));
    return y;
}
// bf16 split: f = hi + lo; hi = truncate-to-bf16 (exact), lo = rn(residual)
__device__ __forceinline__ uint32_t hi2(float f0, float f1) {  // {bf16(f0)|bf16(f1)<<16}
    uint32_t r;
    asm("prmt.b32 %0, %1, %2, 0x7632;" : "=r"(r)
        : "r"(__float_as_uint(f0)), "r"(__float_as_uint(f1)));
    return r;
}
__device__ __forceinline__ float hif(float f) {
    return __uint_as_float(__float_as_uint(f) & 0xFFFF0000u);
}
__device__ __forceinline__ uint32_t lo2(float f0, float f1) {
    uint32_t r;
    asm("cvt.rn.bf16x2.f32 %0, %1, %2;" : "=r"(r)
        : "f"(f1 - hif(f1)), "f"(f0 - hif(f0)));
    return r;
}

__device__ __forceinline__ void ldmx4t(uint32_t addr, uint32_t& r0, uint32_t& r1,
                                       uint32_t& r2, uint32_t& r3) {
    asm volatile("ldmatrix.sync.aligned.m8n8.x4.trans.shared.b16 {%0,%1,%2,%3}, [%4];"
                 : "=r"(r0), "=r"(r1), "=r"(r2), "=r"(r3) : "r"(addr));
}
__device__ __forceinline__ void ldmx4(uint32_t addr, uint32_t* r) {
    asm volatile("ldmatrix.sync.aligned.m8n8.x4.shared.b16 {%0,%1,%2,%3}, [%4];"
                 : "=r"(r[0]), "=r"(r[1]), "=r"(r[2]), "=r"(r[3]) : "r"(addr));
}
__device__ __forceinline__ void mma16816(float* d, const uint32_t* a, const uint32_t* b) {
    asm volatile("mma.sync.aligned.m16n8k16.row.col.f32.bf16.bf16.f32 "
                 "{%0,%1,%2,%3}, {%4,%5,%6,%7}, {%8,%9}, {%0,%1,%2,%3};"
                 : "+f"(d[0]), "+f"(d[1]), "+f"(d[2]), "+f"(d[3])
                 : "r"(a[0]), "r"(a[1]), "r"(a[2]), "r"(a[3]), "r"(b[0]), "r"(b[1]));
}
__device__ __forceinline__ void mma_b(float* d, const uint32_t* a, uint32_t b0, uint32_t b1) {
    asm volatile("mma.sync.aligned.m16n8k16.row.col.f32.bf16.bf16.f32 "
                 "{%0,%1,%2,%3}, {%4,%5,%6,%7}, {%8,%9}, {%0,%1,%2,%3};"
                 : "+f"(d[0]), "+f"(d[1]), "+f"(d[2]), "+f"(d[3])
                 : "r"(a[0]), "r"(a[1]), "r"(a[2]), "r"(a[3]), "r"(b0), "r"(b1));
}

// ---------------------------------------------------------------------------
// Kernel 1: QKV GEMM via tensor cores (bf16x3 split).  (R7 version, 138us)
// ---------------------------------------------------------------------------
#define KTILE  (32 * 136)
#define KBYTES (KTILE * 2)
#define BUFBYTES (4 * KBYTES)

__global__ __launch_bounds__(256) void k_qkv(const float* __restrict__ x,
                                             const float* __restrict__ Wq,
                                             const float* __restrict__ bq)
{
    extern __shared__ __align__(16) uint16_t smq[];

    const int tid  = threadIdx.x;
    const int lane = tid & 31;
    const int wid  = tid >> 5;
    const int bx   = blockIdx.x;
    const int by   = blockIdx.y;
    const int b    = by >> 3;
    const int n0   = (by & 7) << 7;
    const int c0   = bx * 128;

    const uint32_t sbase = (uint32_t)__cvta_generic_to_shared(smq);

    const int lk  = tid >> 3;
    const int lmf = (tid & 7) * 4;

    const float* pA = x  + (size_t)b * CC * NN + (size_t)lk * NN + n0 + lmf;
    const float* pW = Wq + (size_t)lk * QKVC + c0 + lmf;

    const int wm = wid >> 2;
    const int wn = wid & 3;
    const uint32_t aOff = ((lane & 7) + ((lane >> 4) << 3)) * 272
                        + (uint32_t)(wm * 128) + ((lane >> 3) & 1) * 16;
    const uint32_t bOff = ((lane & 7) + (((lane >> 3) & 1) << 3)) * 272
                        + (uint32_t)(wn * 64) + (lane >> 4) * 16;

    float acc[4][4][4];
#pragma unroll
    for (int i = 0; i < 4; i++)
#pragma unroll
        for (int j = 0; j < 4; j++)
#pragma unroll
            for (int e = 0; e < 4; e++) acc[i][j][e] = 0.f;

    {
        uint16_t* s = smq;
        float4 a4[4], w4[4];
#pragma unroll
        for (int j = 0; j < 4; j++) {
            a4[j] = *(const float4*)&pA[32 * j];
            w4[j] = *(const float4*)&pW[32 * j];
        }
#pragma unroll
        for (int j = 0; j < 4; j++) {
            int idx = lk * 136 + lmf + 32 * j;
            *(uint2*)&s[idx]             = make_uint2(hi2(a4[j].x, a4[j].y), hi2(a4[j].z, a4[j].w));
            *(uint2*)&s[KTILE + idx]     = make_uint2(lo2(a4[j].x, a4[j].y), lo2(a4[j].z, a4[j].w));
            *(uint2*)&s[2 * KTILE + idx] = make_uint2(hi2(w4[j].x, w4[j].y), hi2(w4[j].z, w4[j].w));
            *(uint2*)&s[3 * KTILE + idx] = make_uint2(lo2(w4[j].x, w4[j].y), lo2(w4[j].z, w4[j].w));
        }
    }
    __syncthreads();

    for (int s = 0; s < 16; s++) {
        const int cur = s & 1;
        float4 a4[4], w4[4];
        if (s < 15) {
            const size_t ko = (size_t)(s + 1) * 32;
#pragma unroll
            for (int j = 0; j < 4; j++) {
                a4[j] = *(const float4*)&pA[ko * NN + 32 * j];
                w4[j] = *(const float4*)&pW[ko * QKVC + 32 * j];
            }
        }

        const uint32_t base = sbase + (uint32_t)cur * BUFBYTES;
#pragma unroll
        for (int ks = 0; ks < 2; ks++) {
            uint32_t ahi[4][4], alo[4][4], bhi[4][2], blo[4][2];
#pragma unroll
            for (int i = 0; i < 4; i++) {
                uint32_t addr = base + aOff + ks * 4352 + i * 32;
                ldmx4t(addr, ahi[i][0], ahi[i][1], ahi[i][2], ahi[i][3]);
                ldmx4t(addr + KBYTES, alo[i][0], alo[i][1], alo[i][2], alo[i][3]);
            }
#pragma unroll
            for (int j2 = 0; j2 < 2; j2++) {
                uint32_t addr = base + 2 * KBYTES + bOff + ks * 4352 + j2 * 32;
                ldmx4t(addr, bhi[2 * j2][0], bhi[2 * j2][1], bhi[2 * j2 + 1][0], bhi[2 * j2 + 1][1]);
                ldmx4t(addr + KBYTES, blo[2 * j2][0], blo[2 * j2][1], blo[2 * j2 + 1][0], blo[2 * j2 + 1][1]);
            }
#pragma unroll
            for (int i = 0; i < 4; i++)
#pragma unroll
                for (int jn = 0; jn < 4; jn++) {
                    mma16816(acc[i][jn], ahi[i], bhi[jn]);
                    mma16816(acc[i][jn], ahi[i], blo[jn]);
                    mma16816(acc[i][jn], alo[i], bhi[jn]);
                }
        }

        if (s < 15) {
            uint16_t* d = smq + (1 - cur) * (BUFBYTES / 2);
#pragma unroll
            for (int j = 0; j < 4; j++) {
                int idx = lk * 136 + lmf + 32 * j;
                *(uint2*)&d[idx]             = make_uint2(hi2(a4[j].x, a4[j].y), hi2(a4[j].z, a4[j].w));
                *(uint2*)&d[KTILE + idx]     = make_uint2(lo2(a4[j].x, a4[j].y), lo2(a4[j].z, a4[j].w));
                *(uint2*)&d[2 * KTILE + idx] = make_uint2(hi2(w4[j].x, w4[j].y), hi2(w4[j].z, w4[j].w));
                *(uint2*)&d[3 * KTILE + idx] = make_uint2(lo2(w4[j].x, w4[j].y), lo2(w4[j].z, w4[j].w));
            }
            __syncthreads();
        }
    }

    const int g   = lane >> 2;
    const int tig = lane & 3;
#pragma unroll
    for (int i = 0; i < 4; i++) {
        int m = by * 128 + wm * 64 + i * 16 + g;
#pragma unroll
        for (int jn = 0; jn < 4; jn++) {
            int c = c0 + wn * 32 + jn * 8 + tig * 2;
            float2 bias = *(const float2*)&bq[c];
            float2 v0 = make_float2(acc[i][jn][0] + bias.x, acc[i][jn][1] + bias.y);
            float2 v1 = make_float2(acc[i][jn][2] + bias.x, acc[i][jn][3] + bias.y);
            *(float2*)&g_qkv[(size_t)m * QKVC + c]       = v0;
            *(float2*)&g_qkv[(size_t)(m + 8) * QKVC + c] = v1;
        }
    }
}

// ---------------------------------------------------------------------------
// Kernel 2: attention via tensor cores (bf16x3 split), no online softmax.
// V kept NATURAL [key][d] in smem; PV B-fragments via trans-ldmatrix (k_qkv
// pattern) — removes the 64-scalar-STS manual transpose of R7/R8.
// Fused S->exp->P->PV per 16-key group.
// ---------------------------------------------------------------------------
#define AQ_STR 72          // u16 stride for all tiles (144 B rows)
#define A_QLO  9216        // u16 offsets
#define A_KHI  18432
#define A_KLO  27648
#define A_VHI  36864
#define A_VLO  46080
#define A_SMEM_BYTES 110592

__global__ __launch_bounds__(256, 1) void k_attn()
{
    extern __shared__ __align__(16) uint16_t sma[];
    const int tid  = threadIdx.x;
    const int lane = tid & 31;
    const int wid  = tid >> 5;
    const int qt   = blockIdx.x;   // 0..7
    const int h    = blockIdx.y;
    const int b    = blockIdx.z;
    const size_t head = (size_t)b * NN * QKVC + (size_t)h * (3 * DK);
    const uint32_t sb = (uint32_t)__cvta_generic_to_shared(sma);

    // ---- load Q tile (scaled), split to bf16 hi/lo ----
    {
        const int row = tid >> 1;
        const int d0  = (tid & 1) * 32;
        const float* src = &g_qkv[head + (size_t)(qt * 128 + row) * QKVC + d0];
        uint16_t* qh = sma + row * AQ_STR + d0;
#pragma unroll
        for (int i = 0; i < 8; i++) {
            float4 v = *(const float4*)&src[4 * i];
            v.x *= SCL2E; v.y *= SCL2E; v.z *= SCL2E; v.w *= SCL2E;
            *(uint2*)&qh[4 * i]         = make_uint2(hi2(v.x, v.y), hi2(v.z, v.w));
            *(uint2*)&qh[A_QLO + 4 * i] = make_uint2(lo2(v.x, v.y), lo2(v.z, v.w));
        }
    }
    __syncthreads();

    // ---- Q fragments, loaded once: [plane][kstep][4] ----
    uint32_t qf[2][4][4];
    {
        const uint32_t qa = sb + (wid * 16 + (lane & 15)) * 144 + (lane >> 4) * 16;
#pragma unroll
        for (int j = 0; j < 4; j++) {
            ldmx4(qa + j * 32, qf[0][j]);
            ldmx4(qa + j * 32 + A_QLO * 2, qf[1][j]);
        }
    }

    float oacc[8][4];
#pragma unroll
    for (int i = 0; i < 8; i++)
#pragma unroll
        for (int e = 0; e < 4; e++) oacc[i][e] = 0.f;
    float li0 = 0.f, li1 = 0.f;

    // K fragments (B of S=Q@K^T): non-trans, rows = keys
    const uint32_t kB = sb + A_KHI * 2 + ((lane & 7) + ((lane >> 4) << 3)) * 144
                      + ((lane >> 3) & 1) * 16;
    // V fragments (B of O=P@V): trans-ldmatrix on natural [key][d]
    const uint32_t vB = sb + A_VHI * 2 + ((lane & 7) + (((lane >> 3) & 1) << 3)) * 144
                      + (lane >> 4) * 16;

    for (int kt = 0; kt < 8; kt++) {
        __syncthreads();   // previous iteration's smem reads done
        {
            const int key = tid >> 1;
            const int d0  = (tid & 1) * 32;
            const float* kp = &g_qkv[head + (size_t)(kt * 128 + key) * QKVC + 64 + d0];
            uint16_t* khp = sma + A_KHI + key * AQ_STR + d0;
            uint16_t* vhp = sma + A_VHI + key * AQ_STR + d0;
#pragma unroll
            for (int i = 0; i < 8; i++) {
                float4 v = *(const float4*)&kp[4 * i];
                *(uint2*)&khp[4 * i]                   = make_uint2(hi2(v.x, v.y), hi2(v.z, v.w));
                *(uint2*)&khp[(A_KLO - A_KHI) + 4 * i] = make_uint2(lo2(v.x, v.y), lo2(v.z, v.w));
            }
            const float* vp = kp + 64;
#pragma unroll
            for (int i = 0; i < 8; i++) {
                float4 v = *(const float4*)&vp[4 * i];
                *(uint2*)&vhp[4 * i]                   = make_uint2(hi2(v.x, v.y), hi2(v.z, v.w));
                *(uint2*)&vhp[(A_VLO - A_VHI) + 4 * i] = make_uint2(lo2(v.x, v.y), lo2(v.z, v.w));
            }
        }
        __syncthreads();

        // ---- fused per 16-key group: S (2 n8-tiles) -> exp -> P -> PV ----
#pragma unroll
        for (int nt2 = 0; nt2 < 8; nt2++) {
            float s0[4], s1[4];
#pragma unroll
            for (int e = 0; e < 4; e++) { s0[e] = 0.f; s1[e] = 0.f; }

#pragma unroll
            for (int j = 0; j < 4; j++) {
                uint32_t kh[4], kl[4];
                uint32_t a = kB + nt2 * (16 * 144) + j * 32;
                ldmx4(a, kh);
                ldmx4(a + (A_KLO - A_KHI) * 2, kl);
                mma_b(s0, qf[0][j], kh[0], kh[1]);
                mma_b(s0, qf[0][j], kl[0], kl[1]);
                mma_b(s0, qf[1][j], kh[0], kh[1]);
                mma_b(s1, qf[0][j], kh[2], kh[3]);
                mma_b(s1, qf[0][j], kl[2], kl[3]);
                mma_b(s1, qf[1][j], kh[2], kh[3]);
            }

#pragma unroll
            for (int e = 0; e < 4; e++) { s0[e] = ex2(s0[e]); s1[e] = ex2(s1[e]); }
            li0 += (s0[0] + s0[1]) + (s1[0] + s1[1]);
            li1 += (s0[2] + s0[3]) + (s1[2] + s1[3]);

            uint32_t ph[4], pl[4];
            ph[0] = hi2(s0[0], s0[1]); ph[1] = hi2(s0[2], s0[3]);
            ph[2] = hi2(s1[0], s1[1]); ph[3] = hi2(s1[2], s1[3]);
            pl[0] = lo2(s0[0], s0[1]); pl[1] = lo2(s0[2], s0[3]);
            pl[2] = lo2(s1[0], s1[1]); pl[3] = lo2(s1[2], s1[3]);

            // PV: key-step = nt2 (16 keys); d-tiles via trans-ldmatrix
#pragma unroll
            for (int dt2 = 0; dt2 < 4; dt2++) {
                uint32_t vh0, vh1, vh2, vh3, vl0, vl1, vl2, vl3;
                uint32_t a = vB + nt2 * (16 * 144) + dt2 * 32;
                ldmx4t(a, vh0, vh1, vh2, vh3);
                ldmx4t(a + (A_VLO - A_VHI) * 2, vl0, vl1, vl2, vl3);
                mma_b(oacc[2 * dt2],     ph, vh0, vh1);
                mma_b(oacc[2 * dt2],     ph, vl0, vl1);
                mma_b(oacc[2 * dt2],     pl, vh0, vh1);
                mma_b(oacc[2 * dt2 + 1], ph, vh2, vh3);
                mma_b(oacc[2 * dt2 + 1], ph, vl2, vl3);
                mma_b(oacc[2 * dt2 + 1], pl, vh2, vh3);
            }
        }
    }

    // ---- reduce row sums over the 4 quad lanes, normalize, write ----
    li0 += __shfl_xor_sync(0xffffffffu, li0, 1);
    li0 += __shfl_xor_sync(0xffffffffu, li0, 2);
    li1 += __shfl_xor_sync(0xffffffffu, li1, 1);
    li1 += __shfl_xor_sync(0xffffffffu, li1, 2);
    const float inv0 = 1.f / li0;
    const float inv1 = 1.f / li1;

    const int g   = lane >> 2;
    const int tig = lane & 3;
    const int row = qt * 128 + wid * 16 + g;
    float* dst0 = &g_att[((size_t)(b * NN + row)) * CC + h * 64 + tig * 2];
    float* dst1 = dst0 + (size_t)8 * CC;
#pragma unroll
    for (int dt = 0; dt < 8; dt++) {
        *(float2*)&dst0[dt * 8] = make_float2(oacc[dt][0] * inv0, oacc[dt][1] * inv0);
        *(float2*)&dst1[dt * 8] = make_float2(oacc[dt][2] * inv1, oacc[dt][3] * inv1);
    }
}

// ---------------------------------------------------------------------------
// Kernel 3: out = att @ W_out + b_out + residual via tensor cores (bf16x3).
// (R7 version)
// ---------------------------------------------------------------------------
#define PJ_ALO    10240    // byte offsets within a stage
#define PJ_BHI    20480
#define PJ_BLO    29184
#define PJ_STAGEB 37888
#define PJ_SMEM   (2 * PJ_STAGEB)   // 75776 B

__global__ __launch_bounds__(256, 1) void k_proj(const float* __restrict__ Wo,
                                                 const float* __restrict__ bo,
                                                 const float* __restrict__ x,
                                                 float* __restrict__ out)
{
    extern __shared__ __align__(16) uint16_t smp[];
    const int tid  = threadIdx.x;
    const int lane = tid & 31;
    const int wid  = tid >> 5;
    const int bx   = blockIdx.x;    // bn tile 0..63
    const int by   = blockIdx.y;    // c tile 0..3
    const int b    = bx >> 3;
    const int c0   = by * 128;
    const int bn0  = bx * 128;
    const uint32_t sb = (uint32_t)__cvta_generic_to_shared(smp);

    const int am = tid >> 1;
    const int ak = (tid & 1) * 16;
    const float* pA = g_att + (size_t)(bn0 + am) * CC + ak;
    const int bk = tid >> 3;
    const int bn = (tid & 7) * 4;
    const float* pB = Wo + (size_t)bk * CC + c0 + bn;

    const int wm = wid >> 2;
    const int wn = wid & 3;
    const uint32_t aOff = (wm * 64 + (lane & 15)) * 80 + (lane >> 4) * 16;
    const uint32_t bOff = PJ_BHI + ((lane & 7) + (((lane >> 3) & 1) << 3)) * 272
                        + (uint32_t)(wn * 64) + (lane >> 4) * 16;

    float acc[4][4][4];
#pragma unroll
    for (int i = 0; i < 4; i++)
#pragma unroll
        for (int j = 0; j < 4; j++)
#pragma unroll
            for (int e = 0; e < 4; e++) acc[i][j][e] = 0.f;

    {
        uint16_t* s = smp;
#pragma unroll
        for (int i = 0; i < 4; i++) {
            float4 v = *(const float4*)&pA[4 * i];
            int ai = am * 40 + ak + 4 * i;
            *(uint2*)&s[ai]              = make_uint2(hi2(v.x, v.y), hi2(v.z, v.w));
            *(uint2*)&s[PJ_ALO / 2 + ai] = make_uint2(lo2(v.x, v.y), lo2(v.z, v.w));
            float4 w = *(const float4*)&pB[32 * i];
            int bi = bk * 136 + bn + 32 * i;
            *(uint2*)&s[PJ_BHI / 2 + bi] = make_uint2(hi2(w.x, w.y), hi2(w.z, w.w));
            *(uint2*)&s[PJ_BLO / 2 + bi] = make_uint2(lo2(w.x, w.y), lo2(w.z, w.w));
        }
    }
    __syncthreads();

    for (int s = 0; s < 16; s++) {
        const int cur = s & 1;
        float4 a4[4], w4[4];
        if (s < 15) {
#pragma unroll
            for (int i = 0; i < 4; i++) {
                a4[i] = *(const float4*)&pA[(s + 1) * 32 + 4 * i];
                w4[i] = *(const float4*)&pB[(size_t)(s + 1) * 32 * CC + 32 * i];
            }
        }

        const uint32_t base = sb + (uint32_t)cur * PJ_STAGEB;
#pragma unroll
        for (int ks = 0; ks < 2; ks++) {
            uint32_t ahi[4][4], alo[4][4], bhi[4][2], blo[4][2];
#pragma unroll
            for (int i = 0; i < 4; i++) {
                uint32_t a = base + aOff + i * (16 * 80) + ks * 32;
                ldmx4(a, ahi[i]);
                ldmx4(a + PJ_ALO, alo[i]);
            }
#pragma unroll
            for (int j2 = 0; j2 < 2; j2++) {
                uint32_t a = base + bOff + ks * 4352 + j2 * 32;
                ldmx4t(a, bhi[2 * j2][0], bhi[2 * j2][1], bhi[2 * j2 + 1][0], bhi[2 * j2 + 1][1]);
                ldmx4t(a + 8704, blo[2 * j2][0], blo[2 * j2][1], blo[2 * j2 + 1][0], blo[2 * j2 + 1][1]);
            }
#pragma unroll
            for (int i = 0; i < 4; i++)
#pragma unroll
                for (int jn = 0; jn < 4; jn++) {
                    mma16816(acc[i][jn], ahi[i], bhi[jn]);
                    mma16816(acc[i][jn], ahi[i], blo[jn]);
                    mma16816(acc[i][jn], alo[i], bhi[jn]);
                }
        }

        if (s < 15) {
            uint16_t* d = smp + (1 - cur) * (PJ_STAGEB / 2);
#pragma unroll
            for (int i = 0; i < 4; i++) {
                int ai = am * 40 + ak + 4 * i;
                *(uint2*)&d[ai]              = make_uint2(hi2(a4[i].x, a4[i].y), hi2(a4[i].z, a4[i].w));
                *(uint2*)&d[PJ_ALO / 2 + ai] = make_uint2(lo2(a4[i].x, a4[i].y), lo2(a4[i].z, a4[i].w));
                int bi = bk * 136 + bn + 32 * i;
                *(uint2*)&d[PJ_BHI / 2 + bi] = make_uint2(hi2(w4[i].x, w4[i].y), hi2(w4[i].z, w4[i].w));
                *(uint2*)&d[PJ_BLO / 2 + bi] = make_uint2(lo2(w4[i].x, w4[i].y), lo2(w4[i].z, w4[i].w));
            }
            __syncthreads();
        }
    }

    // ---- epilogue: transpose via smem, fused bias + residual, coalesced ----
    __syncthreads();
    float* S = (float*)smp;   // [128 c][stride 132] of m
    const int g   = lane >> 2;
    const int tig = lane & 3;
#pragma unroll
    for (int i = 0; i < 4; i++) {
        int m_l = wm * 64 + i * 16 + g;
#pragma unroll
        for (int jn = 0; jn < 4; jn++) {
            int c_l = wn * 32 + jn * 8 + tig * 2;
            S[c_l * 132 + m_l]           = acc[i][jn][0];
            S[(c_l + 1) * 132 + m_l]     = acc[i][jn][1];
            S[c_l * 132 + m_l + 8]       = acc[i][jn][2];
            S[(c_l + 1) * 132 + m_l + 8] = acc[i][jn][3];
        }
    }
    __syncthreads();
    {
        const int c_l  = tid >> 1;
        const int mseg = (tid & 1) * 64;
        const int c    = c0 + c_l;
        const float bias = bo[c];
        const int n0 = (bx & 7) * 128;
        const size_t basep = (size_t)b * CC * NN + (size_t)c * NN + n0 + mseg;
#pragma unroll
        for (int i = 0; i < 16; i++) {
            float4 v  = *(float4*)&S[c_l * 132 + mseg + 4 * i];
            float4 xr = *(const float4*)&x[basep + 4 * i];
            v.x += bias + xr.x; v.y += bias + xr.y;
            v.z += bias + xr.z; v.w += bias + xr.w;
            *(float4*)&out[basep + 4 * i] = v;
        }
    }
}

// ---------------------------------------------------------------------------
extern "C" void kernel_launch(void* const* d_in, const int* in_sizes, int n_in,
                              void* d_out, int out_size)
{
    const float* x  = (const float*)d_in[0];
    const float* Wq = (const float*)d_in[1];
    const float* bq = (const float*)d_in[2];
    const float* Wo = (const float*)d_in[3];
    const float* bo = (const float*)d_in[4];
    float* out = (float*)d_out;

    const int smem_qkv = 2 * BUFBYTES;   // 69632 B
    cudaFuncSetAttribute(k_qkv, cudaFuncAttributeMaxDynamicSharedMemorySize, smem_qkv);
    k_qkv<<<dim3(12, 64), 256, smem_qkv>>>(x, Wq, bq);

    cudaFuncSetAttribute(k_attn, cudaFuncAttributeMaxDynamicSharedMemorySize, A_SMEM_BYTES);
    k_attn<<<dim3(8, HEADS, BB), 256, A_SMEM_BYTES>>>();

    cudaFuncSetAttribute(k_proj, cudaFuncAttributeMaxDynamicSharedMemorySize, PJ_SMEM);
    k_proj<<<dim3(64, 4), 256, PJ_SMEM>>>(Wo, bo, x, out);
}

// round 10
// speedup vs baseline: 1.1855x; 1.0563x over previous
#include <cuda_runtime.h>
#include <math.h>
#include <stdint.h>

// Problem constants
#define BB    8
#define CC    512
#define NN    1024        // H*W = 32*32
#define HEADS 8
#define DK    64
#define QKVC  1536        // HEADS * DK * 3
#define SCL2E 0.18033688f // DK^-0.5 * log2(e)

// ---------------------------------------------------------------------------
// Scratch (device globals; no allocation allowed) — bf16 hi/lo planes
// ---------------------------------------------------------------------------
__device__ uint16_t g_xh[BB * CC * NN],  g_xl[BB * CC * NN];    // x split
__device__ uint16_t g_wqh[CC * QKVC],    g_wql[CC * QKVC];      // W_qkv split
__device__ uint16_t g_woh[CC * CC],      g_wol[CC * CC];        // W_out split
__device__ uint16_t g_qh[BB * NN * QKVC], g_ql[BB * NN * QKVC]; // qkv (Q pre-scaled)
__device__ uint16_t g_ah[BB * NN * CC],  g_al[BB * NN * CC];    // attention out

// ---------------------------------------------------------------------------
// Helpers
// ---------------------------------------------------------------------------
__device__ __forceinline__ float ex2(float x) {
    float y;
    asm("ex2.approx.f32 %0, %1;" : "=f"(y) : "f"(x));
    return y;
}
// bf16 split: f = hi + lo; hi = truncate-to-bf16 (exact), lo = rn(residual)
__device__ __forceinline__ uint32_t hi2(float f0, float f1) {
    uint32_t r;
    asm("prmt.b32 %0, %1, %2, 0x7632;" : "=r"(r)
        : "r"(__float_as_uint(f0)), "r"(__float_as_uint(f1)));
    return r;
}
__device__ __forceinline__ float hif(float f) {
    return __uint_as_float(__float_as_uint(f) & 0xFFFF0000u);
}
__device__ __forceinline__ uint32_t lo2(float f0, float f1) {
    uint32_t r;
    asm("cvt.rn.bf16x2.f32 %0, %1, %2;" : "=r"(r)
        : "f"(f1 - hif(f1)), "f"(f0 - hif(f0)));
    return r;
}

__device__ __forceinline__ void cpa16(uint32_t dst, const void* src) {
    asm volatile("cp.async.cg.shared.global [%0], [%1], 16;" :: "r"(dst), "l"(src));
}
#define CP_COMMIT() asm volatile("cp.async.commit_group;" ::: "memory")
#define CP_WAIT1()  asm volatile("cp.async.wait_group 1;" ::: "memory")
#define CP_WAIT0()  asm volatile("cp.async.wait_group 0;" ::: "memory")

__device__ __forceinline__ void ldmx4t(uint32_t addr, uint32_t& r0, uint32_t& r1,
                                       uint32_t& r2, uint32_t& r3) {
    asm volatile("ldmatrix.sync.aligned.m8n8.x4.trans.shared.b16 {%0,%1,%2,%3}, [%4];"
                 : "=r"(r0), "=r"(r1), "=r"(r2), "=r"(r3) : "r"(addr));
}
__device__ __forceinline__ void ldmx4(uint32_t addr, uint32_t* r) {
    asm volatile("ldmatrix.sync.aligned.m8n8.x4.shared.b16 {%0,%1,%2,%3}, [%4];"
                 : "=r"(r[0]), "=r"(r[1]), "=r"(r[2]), "=r"(r[3]) : "r"(addr));
}
__device__ __forceinline__ void mma16816(float* d, const uint32_t* a, const uint32_t* b) {
    asm volatile("mma.sync.aligned.m16n8k16.row.col.f32.bf16.bf16.f32 "
                 "{%0,%1,%2,%3}, {%4,%5,%6,%7}, {%8,%9}, {%0,%1,%2,%3};"
                 : "+f"(d[0]), "+f"(d[1]), "+f"(d[2]), "+f"(d[3])
                 : "r"(a[0]), "r"(a[1]), "r"(a[2]), "r"(a[3]), "r"(b[0]), "r"(b[1]));
}
__device__ __forceinline__ void mma_b(float* d, const uint32_t* a, uint32_t b0, uint32_t b1) {
    asm volatile("mma.sync.aligned.m16n8k16.row.col.f32.bf16.bf16.f32 "
                 "{%0,%1,%2,%3}, {%4,%5,%6,%7}, {%8,%9}, {%0,%1,%2,%3};"
                 : "+f"(d[0]), "+f"(d[1]), "+f"(d[2]), "+f"(d[3])
                 : "r"(a[0]), "r"(a[1]), "r"(a[2]), "r"(a[3]), "r"(b0), "r"(b1));
}

// ---------------------------------------------------------------------------
// Kernel 0: fp32 -> bf16 hi/lo plane split (pre-pass; tiny, memory bound)
// ---------------------------------------------------------------------------
__global__ __launch_bounds__(256) void k_cvt(const float* __restrict__ src,
                                             int which, int n4)
{
    uint16_t *h, *l;
    if (which == 0)      { h = g_xh;  l = g_xl;  }
    else if (which == 1) { h = g_wqh; l = g_wql; }
    else                 { h = g_woh; l = g_wol; }
    int i = blockIdx.x * blockDim.x + threadIdx.x;
    if (i < n4) {
        float4 v = ((const float4*)src)[i];
        ((uint2*)h)[i] = make_uint2(hi2(v.x, v.y), hi2(v.z, v.w));
        ((uint2*)l)[i] = make_uint2(lo2(v.x, v.y), lo2(v.z, v.w));
    }
}

// ---------------------------------------------------------------------------
// Kernel 1: QKV GEMM via tensor cores (bf16x3 split), cp.async 3-stage.
// C[m=8192][c=1536] = x^T @ Wq + bq.  Output: bf16 hi/lo planes, Q pre-scaled.
// Smem per stage: Ahi/Alo/Whi/Wlo, each 32 k-rows x 128 u16, row stride 272B.
// ---------------------------------------------------------------------------
#define KBYTES  8704            // one plane: 32 * 272 B
#define QK_STG  (4 * KBYTES)    // 34816 B per stage
#define QK_SMEM (3 * QK_STG)    // 104448 B

__global__ __launch_bounds__(256) void k_qkv(const float* __restrict__ bq)
{
    extern __shared__ __align__(16) uint16_t smq[];
    const int tid  = threadIdx.x;
    const int lane = tid & 31;
    const int wid  = tid >> 5;
    const int bx   = blockIdx.x;          // c tile 0..11
    const int by   = blockIdx.y;          // m tile 0..63
    const int b    = by >> 3;
    const int n0   = (by & 7) << 7;
    const int c0   = bx * 128;
    const uint32_t sbase = (uint32_t)__cvta_generic_to_shared(smq);

    // loader mapping: row lk (0..31), 16 u16 (32B) per plane per matrix
    const int lk  = tid >> 3;
    const int lmf = (tid & 7) * 16;       // u16 offset in 128-wide row
    const size_t aG = (size_t)b * CC * NN + n0 + lmf + (size_t)lk * NN;   // + k0*NN
    const size_t wG = (size_t)c0 + lmf + (size_t)lk * QKVC;               // + k0*QKVC
    const uint32_t dA = (uint32_t)(lk * 136 + lmf) * 2;  // byte offset in plane

    const int wm = wid >> 2;
    const int wn = wid & 3;
    const uint32_t aOff = ((lane & 7) + ((lane >> 4) << 3)) * 272
                        + (uint32_t)(wm * 128) + ((lane >> 3) & 1) * 16;
    const uint32_t bOff = ((lane & 7) + (((lane >> 3) & 1) << 3)) * 272
                        + (uint32_t)(wn * 64) + (lane >> 4) * 16;

    float acc[4][4][4];
#pragma unroll
    for (int i = 0; i < 4; i++)
#pragma unroll
        for (int j = 0; j < 4; j++)
#pragma unroll
            for (int e = 0; e < 4; e++) acc[i][j][e] = 0.f;

#define QK_ISSUE(s) do {                                                      \
        uint32_t st = sbase + ((s) % 3) * QK_STG;                             \
        size_t ko = (size_t)(s) * 32;                                         \
        const uint16_t* ah = &g_xh[aG + ko * NN];                             \
        const uint16_t* al = &g_xl[aG + ko * NN];                             \
        const uint16_t* wh = &g_wqh[wG + ko * QKVC];                          \
        const uint16_t* wl = &g_wql[wG + ko * QKVC];                          \
        cpa16(st + dA, ah);                   cpa16(st + dA + 16, ah + 8);    \
        cpa16(st + dA + KBYTES, al);          cpa16(st + dA + KBYTES + 16, al + 8); \
        cpa16(st + dA + 2 * KBYTES, wh);      cpa16(st + dA + 2 * KBYTES + 16, wh + 8); \
        cpa16(st + dA + 3 * KBYTES, wl);      cpa16(st + dA + 3 * KBYTES + 16, wl + 8); \
    } while (0)

    QK_ISSUE(0); CP_COMMIT();
    QK_ISSUE(1); CP_COMMIT();

    for (int s = 0; s < 16; s++) {
        if (s < 15) CP_WAIT1(); else CP_WAIT0();
        __syncthreads();
        if (s + 2 < 16) { QK_ISSUE(s + 2); CP_COMMIT(); }

        const uint32_t base = sbase + (uint32_t)(s % 3) * QK_STG;
#pragma unroll
        for (int ks = 0; ks < 2; ks++) {
            uint32_t ahi[4][4], alo[4][4], bhi[4][2], blo[4][2];
#pragma unroll
            for (int i = 0; i < 4; i++) {
                uint32_t addr = base + aOff + ks * 4352 + i * 32;
                ldmx4t(addr, ahi[i][0], ahi[i][1], ahi[i][2], ahi[i][3]);
                ldmx4t(addr + KBYTES, alo[i][0], alo[i][1], alo[i][2], alo[i][3]);
            }
#pragma unroll
            for (int j2 = 0; j2 < 2; j2++) {
                uint32_t addr = base + 2 * KBYTES + bOff + ks * 4352 + j2 * 32;
                ldmx4t(addr, bhi[2 * j2][0], bhi[2 * j2][1], bhi[2 * j2 + 1][0], bhi[2 * j2 + 1][1]);
                ldmx4t(addr + KBYTES, blo[2 * j2][0], blo[2 * j2][1], blo[2 * j2 + 1][0], blo[2 * j2 + 1][1]);
            }
#pragma unroll
            for (int i = 0; i < 4; i++)
#pragma unroll
                for (int jn = 0; jn < 4; jn++) {
                    mma16816(acc[i][jn], ahi[i], bhi[jn]);
                    mma16816(acc[i][jn], ahi[i], blo[jn]);
                    mma16816(acc[i][jn], alo[i], bhi[jn]);
                }
        }
    }

    // ---- epilogue: bias, pre-scale Q columns, split to hi/lo planes ----
    const int g   = lane >> 2;
    const int tig = lane & 3;
#pragma unroll
    for (int i = 0; i < 4; i++) {
        int m = by * 128 + wm * 64 + i * 16 + g;
#pragma unroll
        for (int jn = 0; jn < 4; jn++) {
            int c = c0 + wn * 32 + jn * 8 + tig * 2;
            float2 bias = *(const float2*)&bq[c];
            float sc = ((c % 192) < 64) ? SCL2E : 1.f;
            float v0 = (acc[i][jn][0] + bias.x) * sc;
            float v1 = (acc[i][jn][1] + bias.y) * sc;
            float v2 = (acc[i][jn][2] + bias.x) * sc;
            float v3 = (acc[i][jn][3] + bias.y) * sc;
            size_t i0 = (size_t)m * QKVC + c;
            size_t i1 = (size_t)(m + 8) * QKVC + c;
            *(uint32_t*)&g_qh[i0] = hi2(v0, v1);
            *(uint32_t*)&g_ql[i0] = lo2(v0, v1);
            *(uint32_t*)&g_qh[i1] = hi2(v2, v3);
            *(uint32_t*)&g_ql[i1] = lo2(v2, v3);
        }
    }
}

// ---------------------------------------------------------------------------
// Kernel 2: attention via tensor cores (bf16x3), no online softmax,
// cp.async loaders (no conversions in-loop), double-buffered K/V stages.
// Smem (u16): Qhi[128][72]=9216, Qlo; 2 stages of {Khi,Klo,Vhi,Vlo}[128][72].
// ---------------------------------------------------------------------------
#define A_QLO   9216
#define A_ST0   18432           // u16 offset of stage 0
#define A_STG   36864           // u16 per stage (4 planes * 9216)
#define A_SMEM_BYTES ((A_ST0 + 2 * A_STG) * 2)   // 184320 B

__global__ __launch_bounds__(256, 1) void k_attn()
{
    extern __shared__ __align__(16) uint16_t sma[];
    const int tid  = threadIdx.x;
    const int lane = tid & 31;
    const int wid  = tid >> 5;
    const int qt   = blockIdx.x;   // 0..7
    const int h    = blockIdx.y;
    const int b    = blockIdx.z;
    const size_t head = (size_t)b * NN * QKVC + (size_t)h * (3 * DK);
    const uint32_t sb = (uint32_t)__cvta_generic_to_shared(sma);

    // loader mapping: row = tid>>1 (0..127), off = (tid&1)*32 u16 (64B = 4 chunks)
    const int lrow = tid >> 1;
    const int loff = (tid & 1) * 32;
    const uint32_t dRow = (uint32_t)(lrow * 72 + loff) * 2;   // byte offset in plane

#define AT_ISSUE_Q() do {                                                     \
        size_t r = head + (size_t)(qt * 128 + lrow) * QKVC + loff;            \
        const uint16_t* qh_ = &g_qh[r];                                       \
        const uint16_t* ql_ = &g_ql[r];                                       \
        _Pragma("unroll")                                                     \
        for (int cchunk = 0; cchunk < 4; cchunk++) {                          \
            cpa16(sb + dRow + cchunk * 16, qh_ + cchunk * 8);                 \
            cpa16(sb + dRow + A_QLO * 2 + cchunk * 16, ql_ + cchunk * 8);     \
        }                                                                     \
    } while (0)

#define AT_ISSUE_KV(kt) do {                                                  \
        uint32_t st = sb + (A_ST0 + ((kt) & 1) * A_STG) * 2;                  \
        size_t r = head + (size_t)((kt) * 128 + lrow) * QKVC + loff;          \
        const uint16_t* kh_ = &g_qh[r + 64];                                  \
        const uint16_t* kl_ = &g_ql[r + 64];                                  \
        const uint16_t* vh_ = &g_qh[r + 128];                                 \
        const uint16_t* vl_ = &g_ql[r + 128];                                 \
        _Pragma("unroll")                                                     \
        for (int cchunk = 0; cchunk < 4; cchunk++) {                          \
            cpa16(st + dRow + cchunk * 16,              kh_ + cchunk * 8);    \
            cpa16(st + dRow + 9216 * 2 + cchunk * 16,   kl_ + cchunk * 8);    \
            cpa16(st + dRow + 18432 * 2 + cchunk * 16,  vh_ + cchunk * 8);    \
            cpa16(st + dRow + 27648 * 2 + cchunk * 16,  vl_ + cchunk * 8);    \
        }                                                                     \
    } while (0)

    AT_ISSUE_Q(); AT_ISSUE_KV(0); CP_COMMIT();
    AT_ISSUE_KV(1); CP_COMMIT();

    // per-lane fragment address pieces
    const uint32_t kOff = ((lane & 7) + ((lane >> 4) << 3)) * 144
                        + ((lane >> 3) & 1) * 16;                 // non-trans (K)
    const uint32_t vOff = ((lane & 7) + (((lane >> 3) & 1) << 3)) * 144
                        + (lane >> 4) * 16;                        // trans (V)

    uint32_t qf[2][4][4];
    float oacc[8][4];
#pragma unroll
    for (int i = 0; i < 8; i++)
#pragma unroll
        for (int e = 0; e < 4; e++) oacc[i][e] = 0.f;
    float li0 = 0.f, li1 = 0.f;

    for (int kt = 0; kt < 8; kt++) {
        if (kt < 7) CP_WAIT1(); else CP_WAIT0();
        __syncthreads();

        if (kt == 0) {
            const uint32_t qa = sb + (wid * 16 + (lane & 15)) * 144 + (lane >> 4) * 16;
#pragma unroll
            for (int j = 0; j < 4; j++) {
                ldmx4(qa + j * 32, qf[0][j]);
                ldmx4(qa + j * 32 + A_QLO * 2, qf[1][j]);
            }
        }

        const uint32_t stb = sb + (A_ST0 + (kt & 1) * A_STG) * 2;
        const uint32_t kB = stb + kOff;
        const uint32_t vB = stb + 18432 * 2 + vOff;

        // ---- fused per 16-key group: S (2 n8-tiles) -> exp -> P -> PV ----
#pragma unroll
        for (int nt2 = 0; nt2 < 8; nt2++) {
            float s0[4], s1[4];
#pragma unroll
            for (int e = 0; e < 4; e++) { s0[e] = 0.f; s1[e] = 0.f; }

#pragma unroll
            for (int j = 0; j < 4; j++) {
                uint32_t kh[4], kl[4];
                uint32_t a = kB + nt2 * (16 * 144) + j * 32;
                ldmx4(a, kh);
                ldmx4(a + 9216 * 2, kl);
                mma_b(s0, qf[0][j], kh[0], kh[1]);
                mma_b(s0, qf[0][j], kl[0], kl[1]);
                mma_b(s0, qf[1][j], kh[0], kh[1]);
                mma_b(s1, qf[0][j], kh[2], kh[3]);
                mma_b(s1, qf[0][j], kl[2], kl[3]);
                mma_b(s1, qf[1][j], kh[2], kh[3]);
            }

#pragma unroll
            for (int e = 0; e < 4; e++) { s0[e] = ex2(s0[e]); s1[e] = ex2(s1[e]); }
            li0 += (s0[0] + s0[1]) + (s1[0] + s1[1]);
            li1 += (s0[2] + s0[3]) + (s1[2] + s1[3]);

            uint32_t ph[4], pl[4];
            ph[0] = hi2(s0[0], s0[1]); ph[1] = hi2(s0[2], s0[3]);
            ph[2] = hi2(s1[0], s1[1]); ph[3] = hi2(s1[2], s1[3]);
            pl[0] = lo2(s0[0], s0[1]); pl[1] = lo2(s0[2], s0[3]);
            pl[2] = lo2(s1[0], s1[1]); pl[3] = lo2(s1[2], s1[3]);

#pragma unroll
            for (int dt2 = 0; dt2 < 4; dt2++) {
                uint32_t vh0, vh1, vh2, vh3, vl0, vl1, vl2, vl3;
                uint32_t a = vB + nt2 * (16 * 144) + dt2 * 32;
                ldmx4t(a, vh0, vh1, vh2, vh3);
                ldmx4t(a + 9216 * 2, vl0, vl1, vl2, vl3);
                mma_b(oacc[2 * dt2],     ph, vh0, vh1);
                mma_b(oacc[2 * dt2],     ph, vl0, vl1);
                mma_b(oacc[2 * dt2],     pl, vh0, vh1);
                mma_b(oacc[2 * dt2 + 1], ph, vh2, vh3);
                mma_b(oacc[2 * dt2 + 1], ph, vl2, vl3);
                mma_b(oacc[2 * dt2 + 1], pl, vh2, vh3);
            }
        }

        __syncthreads();   // all reads of stage kt%2 done before refilling it
        if (kt + 2 < 8) { AT_ISSUE_KV(kt + 2); CP_COMMIT(); }
    }

    // ---- reduce row sums over the 4 quad lanes, normalize, write planes ----
    li0 += __shfl_xor_sync(0xffffffffu, li0, 1);
    li0 += __shfl_xor_sync(0xffffffffu, li0, 2);
    li1 += __shfl_xor_sync(0xffffffffu, li1, 1);
    li1 += __shfl_xor_sync(0xffffffffu, li1, 2);
    const float inv0 = 1.f / li0;
    const float inv1 = 1.f / li1;

    const int g   = lane >> 2;
    const int tig = lane & 3;
    const int row = qt * 128 + wid * 16 + g;
    const size_t r0 = (size_t)(b * NN + row) * CC + h * 64 + tig * 2;
    const size_t r1 = r0 + (size_t)8 * CC;
#pragma unroll
    for (int dt = 0; dt < 8; dt++) {
        float a0 = oacc[dt][0] * inv0, a1 = oacc[dt][1] * inv0;
        float a2 = oacc[dt][2] * inv1, a3 = oacc[dt][3] * inv1;
        *(uint32_t*)&g_ah[r0 + dt * 8] = hi2(a0, a1);
        *(uint32_t*)&g_al[r0 + dt * 8] = lo2(a0, a1);
        *(uint32_t*)&g_ah[r1 + dt * 8] = hi2(a2, a3);
        *(uint32_t*)&g_al[r1 + dt * 8] = lo2(a2, a3);
    }
}

// ---------------------------------------------------------------------------
// Kernel 3: out = att @ W_out + b_out + residual via tensor cores (bf16x3),
// cp.async 3-stage; smem-transpose epilogue with fused bias+residual.
// ---------------------------------------------------------------------------
#define PJ_ALO    10240    // byte offsets within a stage
#define PJ_BHI    20480
#define PJ_BLO    29184
#define PJ_STAGEB 37888
#define PJ_SMEM   (3 * PJ_STAGEB)   // 113664 B

__global__ __launch_bounds__(256, 1) void k_proj(const float* __restrict__ bo,
                                                 const float* __restrict__ x,
                                                 float* __restrict__ out)
{
    extern __shared__ __align__(16) uint16_t smp[];
    const int tid  = threadIdx.x;
    const int lane = tid & 31;
    const int wid  = tid >> 5;
    const int bx   = blockIdx.x;    // bn tile 0..63
    const int by   = blockIdx.y;    // c tile 0..3
    const int b    = bx >> 3;
    const int c0   = by * 128;
    const int bn0  = bx * 128;
    const uint32_t sb = (uint32_t)__cvta_generic_to_shared(smp);

    // loader mapping
    const int am = tid >> 1;
    const int ak = (tid & 1) * 16;            // u16
    const size_t aG = (size_t)(bn0 + am) * CC + ak;
    const int bk = tid >> 3;
    const int bn = (tid & 7) * 16;            // u16
    const size_t bG = (size_t)bk * CC + c0 + bn;
    const uint32_t dAp = (uint32_t)(am * 40 + ak) * 2;
    const uint32_t dBp = PJ_BHI + (uint32_t)(bk * 136 + bn) * 2;

#define PJ_ISSUE(s) do {                                                      \
        uint32_t st = sb + ((s) % 3) * PJ_STAGEB;                             \
        const uint16_t* ah = &g_ah[aG + (s) * 32];                            \
        const uint16_t* al = &g_al[aG + (s) * 32];                            \
        const uint16_t* bh = &g_woh[bG + (size_t)(s) * 32 * CC];              \
        const uint16_t* bl = &g_wol[bG + (size_t)(s) * 32 * CC];              \
        cpa16(st + dAp, ah);                cpa16(st + dAp + 16, ah + 8);     \
        cpa16(st + dAp + PJ_ALO, al);       cpa16(st + dAp + PJ_ALO + 16, al + 8); \
        cpa16(st + dBp, bh);                cpa16(st + dBp + 16, bh + 8);     \
        cpa16(st + dBp + 8704, bl);         cpa16(st + dBp + 8704 + 16, bl + 8); \
    } while (0)

    const int wm = wid >> 2;
    const int wn = wid & 3;
    const uint32_t aOff = (wm * 64 + (lane & 15)) * 80 + (lane >> 4) * 16;
    const uint32_t bOff = PJ_BHI + ((lane & 7) + (((lane >> 3) & 1) << 3)) * 272
                        + (uint32_t)(wn * 64) + (lane >> 4) * 16;

    float acc[4][4][4];
#pragma unroll
    for (int i = 0; i < 4; i++)
#pragma unroll
        for (int j = 0; j < 4; j++)
#pragma unroll
            for (int e = 0; e < 4; e++) acc[i][j][e] = 0.f;

    PJ_ISSUE(0); CP_COMMIT();
    PJ_ISSUE(1); CP_COMMIT();

    for (int s = 0; s < 16; s++) {
        if (s < 15) CP_WAIT1(); else CP_WAIT0();
        __syncthreads();
        if (s + 2 < 16) { PJ_ISSUE(s + 2); CP_COMMIT(); }

        const uint32_t base = sb + (uint32_t)(s % 3) * PJ_STAGEB;
#pragma unroll
        for (int ks = 0; ks < 2; ks++) {
            uint32_t ahi[4][4], alo[4][4], bhi[4][2], blo[4][2];
#pragma unroll
            for (int i = 0; i < 4; i++) {
                uint32_t a = base + aOff + i * (16 * 80) + ks * 32;
                ldmx4(a, ahi[i]);
                ldmx4(a + PJ_ALO, alo[i]);
            }
#pragma unroll
            for (int j2 = 0; j2 < 2; j2++) {
                uint32_t a = base + bOff + ks * 4352 + j2 * 32;
                ldmx4t(a, bhi[2 * j2][0], bhi[2 * j2][1], bhi[2 * j2 + 1][0], bhi[2 * j2 + 1][1]);
                ldmx4t(a + 8704, blo[2 * j2][0], blo[2 * j2][1], blo[2 * j2 + 1][0], blo[2 * j2 + 1][1]);
            }
#pragma unroll
            for (int i = 0; i < 4; i++)
#pragma unroll
                for (int jn = 0; jn < 4; jn++) {
                    mma16816(acc[i][jn], ahi[i], bhi[jn]);
                    mma16816(acc[i][jn], ahi[i], blo[jn]);
                    mma16816(acc[i][jn], alo[i], bhi[jn]);
                }
        }
    }

    // ---- epilogue: transpose via smem, fused bias + residual, coalesced ----
    __syncthreads();
    float* S = (float*)smp;   // [128 c][stride 132] of m
    const int g   = lane >> 2;
    const int tig = lane & 3;
#pragma unroll
    for (int i = 0; i < 4; i++) {
        int m_l = wm * 64 + i * 16 + g;
#pragma unroll
        for (int jn = 0; jn < 4; jn++) {
            int c_l = wn * 32 + jn * 8 + tig * 2;
            S[c_l * 132 + m_l]           = acc[i][jn][0];
            S[(c_l + 1) * 132 + m_l]     = acc[i][jn][1];
            S[c_l * 132 + m_l + 8]       = acc[i][jn][2];
            S[(c_l + 1) * 132 + m_l + 8] = acc[i][jn][3];
        }
    }
    __syncthreads();
    {
        const int c_l  = tid >> 1;
        const int mseg = (tid & 1) * 64;
        const int c    = c0 + c_l;
        const float bias = bo[c];
        const int n0 = (bx & 7) * 128;
        const size_t basep = (size_t)b * CC * NN + (size_t)c * NN + n0 + mseg;
#pragma unroll
        for (int i = 0; i < 16; i++) {
            float4 v  = *(float4*)&S[c_l * 132 + mseg + 4 * i];
            float4 xr = *(const float4*)&x[basep + 4 * i];
            v.x += bias + xr.x; v.y += bias + xr.y;
            v.z += bias + xr.z; v.w += bias + xr.w;
            *(float4*)&out[basep + 4 * i] = v;
        }
    }
}

// ---------------------------------------------------------------------------
extern "C" void kernel_launch(void* const* d_in, const int* in_sizes, int n_in,
                              void* d_out, int out_size)
{
    const float* x  = (const float*)d_in[0];
    const float* Wq = (const float*)d_in[1];
    const float* bq = (const float*)d_in[2];
    const float* Wo = (const float*)d_in[3];
    const float* bo = (const float*)d_in[4];
    float* out = (float*)d_out;

    // Pre-pass: split x, Wq, Wo to bf16 hi/lo planes
    k_cvt<<<(BB * CC * NN / 4 + 255) / 256, 256>>>(x, 0, BB * CC * NN / 4);
    k_cvt<<<(CC * QKVC / 4 + 255) / 256, 256>>>(Wq, 1, CC * QKVC / 4);
    k_cvt<<<(CC * CC / 4 + 255) / 256, 256>>>(Wo, 2, CC * CC / 4);

    cudaFuncSetAttribute(k_qkv, cudaFuncAttributeMaxDynamicSharedMemorySize, QK_SMEM);
    k_qkv<<<dim3(12, 64), 256, QK_SMEM>>>(bq);

    cudaFuncSetAttribute(k_attn, cudaFuncAttributeMaxDynamicSharedMemorySize, A_SMEM_BYTES);
    k_attn<<<dim3(8, HEADS, BB), 256, A_SMEM_BYTES>>>();

    cudaFuncSetAttribute(k_proj, cudaFuncAttributeMaxDynamicSharedMemorySize, PJ_SMEM);
    k_proj<<<dim3(64, 4), 256, PJ_SMEM>>>(bo, x, out);
}